// round 16
// baseline (speedup 1.0000x reference)
#include <cuda_runtime.h>
#include <cuda_bf16.h>
#include <cstdint>

// Problem constants
#define MB   256
#define NN   512
#define DD   128
#define C1   256
#define C2   128
#define MTOT (MB * NN)

// ---------------- scratch ----------------
__device__ uint32_t g_Pt[(size_t)MB * 2 * DD * (NN / 2)];
__device__ uint32_t g_Xs[2 * (size_t)MTOT * (C1 / 2)];
__device__ float    g_Y1[(size_t)MTOT * C1];
__device__ uint32_t g_W1s[2 * C1 * (C1 / 2)];
__device__ uint32_t g_W2s[2 * C2 * (C1 / 2)];
__device__ float    g_partS[256 * 1024];
__device__ float    g_partQ[256 * 1024];
__device__ float    g_ab[2 * C1 + 2 * C2];

__device__ __forceinline__ float lrelu(float y) { return y >= 0.f ? y : 0.01f * y; }

// ---------------- helpers ----------------
__device__ __forceinline__ void bsplit(float x, uint16_t& h, uint16_t& l) {
    __nv_bfloat16 hb = __float2bfloat16(x);
    float r = x - __bfloat162float(hb);
    __nv_bfloat16 lb = __float2bfloat16(r);
    h = __bfloat16_as_ushort(hb);
    l = __bfloat16_as_ushort(lb);
}
__device__ __forceinline__ uint32_t pk(uint16_t a, uint16_t b) {
    return (uint32_t)a | ((uint32_t)b << 16);
}
__device__ __forceinline__ uint32_t smem_u32(const void* p) {
    uint32_t a;
    asm("{ .reg .u64 t; cvta.to.shared.u64 t, %1; cvt.u32.u64 %0, t; }" : "=r"(a) : "l"(p));
    return a;
}
__device__ __forceinline__ void cpasync16(uint32_t saddr, const void* g) {
    asm volatile("cp.async.cg.shared.global [%0], [%1], 16;" :: "r"(saddr), "l"(g));
}
#define CP_COMMIT() asm volatile("cp.async.commit_group;" ::: "memory")
#define CP_WAIT0()  asm volatile("cp.async.wait_group 0;" ::: "memory")
#define CP_WAIT1()  asm volatile("cp.async.wait_group 1;" ::: "memory")

__device__ __forceinline__ void mma16816(float* c, const uint32_t* a, const uint32_t* b) {
    asm volatile(
        "mma.sync.aligned.m16n8k16.row.col.f32.bf16.bf16.f32 "
        "{%0,%1,%2,%3}, {%4,%5,%6,%7}, {%8,%9}, {%0,%1,%2,%3};"
        : "+f"(c[0]), "+f"(c[1]), "+f"(c[2]), "+f"(c[3])
        : "r"(a[0]), "r"(a[1]), "r"(a[2]), "r"(a[3]), "r"(b[0]), "r"(b[1]));
}
__device__ __forceinline__ void ldsm4(uint32_t& r0, uint32_t& r1, uint32_t& r2,
                                      uint32_t& r3, uint32_t a) {
    asm volatile("ldmatrix.sync.aligned.m8n8.x4.shared.b16 {%0,%1,%2,%3}, [%4];"
        : "=r"(r0), "=r"(r1), "=r"(r2), "=r"(r3) : "r"(a));
}

#define PLANE 10240u            // bytes per [128][20] u32 plane

__device__ __forceinline__ void pass16(float acc[4][4][4],
                                       uint32_t a[4][4], uint32_t b[2][4]) {
#pragma unroll
    for (int mf = 0; mf < 4; mf++)
#pragma unroll
        for (int nf = 0; nf < 4; nf++)
            mma16816(acc[mf][nf], a[mf], &b[nf >> 1][(nf & 1) * 2]);
}

// ---------------- warp-tile compute over one 32-k chunk (ldmatrix) ----------
__device__ __forceinline__ void compute_chunk(
    uint32_t aB, uint32_t bB, float acc[4][4][4], int wr, int wc, int lane)
{
    const int l7  = lane & 7;
    const int tb0 = (lane >> 3) & 1;
    const int tb1 = (lane >> 4) & 1;
#pragma unroll
    for (int ks = 0; ks < 2; ks++) {
        uint32_t ah[4][4], al[4][4], bh[2][4], bl[2][4];
#pragma unroll
        for (int mf = 0; mf < 4; mf++) {
            uint32_t off = ((uint32_t)(wr * 64 + mf * 16 + tb0 * 8 + l7) * 20
                            + (uint32_t)(ks * 8 + tb1 * 4)) * 4;
            ldsm4(ah[mf][0], ah[mf][1], ah[mf][2], ah[mf][3], aB + off);
            ldsm4(al[mf][0], al[mf][1], al[mf][2], al[mf][3], aB + PLANE + off);
        }
#pragma unroll
        for (int np = 0; np < 2; np++) {
            uint32_t off = ((uint32_t)(wc * 32 + np * 16 + tb1 * 8 + l7) * 20
                            + (uint32_t)(ks * 8 + tb0 * 4)) * 4;
            ldsm4(bh[np][0], bh[np][1], bh[np][2], bh[np][3], bB + off);
            ldsm4(bl[np][0], bl[np][1], bl[np][2], bl[np][3], bB + PLANE + off);
        }
        pass16(acc, ah, bh);
        pass16(acc, ah, bl);
        pass16(acc, al, bh);
    }
}

// ---------------- fused per-CTA BN stats epilogue (deterministic) ----------
__device__ __forceinline__ void stats_epilogue(
    const float acc[4][4][4], int wr, int wc, int lane, int tid,
    float* sPS, float* sPQ, int chBase, int bx)
{
    const int ci = wr * 8 + (lane >> 2);
#pragma unroll
    for (int nf = 0; nf < 4; nf++)
#pragma unroll
        for (int c01 = 0; c01 < 2; c01++) {
            int col = wc * 32 + nf * 8 + (lane & 3) * 2 + c01;
            float s = 0.f, q = 0.f;
#pragma unroll
            for (int mf = 0; mf < 4; mf++) {
                float y0 = acc[mf][nf][c01];
                float y1 = acc[mf][nf][2 + c01];
                s += y0 + y1;
                q += y0 * y0 + y1 * y1;
            }
            sPS[col * 17 + ci] = s;
            sPQ[col * 17 + ci] = q;
        }
    __syncthreads();
    if (tid < 128) {
        float s = 0.f, q = 0.f;
#pragma unroll
        for (int i = 0; i < 16; i++) {
            s += sPS[tid * 17 + i];
            q += sPQ[tid * 17 + i];
        }
        g_partS[(size_t)(chBase + tid) * 1024 + bx] = s;
        g_partQ[(size_t)(chBase + tid) * 1024 + bx] = q;
    }
}

// ============================================================
// kP: P -> transposed split planes g_Pt[b][pa][d][kp]
// ============================================================
__global__ __launch_bounds__(256) void kP_split(const float* __restrict__ P)
{
    __shared__ uint16_t sH16[128][66];
    __shared__ uint16_t sL16[128][66];

    const int tid = threadIdx.x;
    const int b   = blockIdx.x;
    const int kt  = blockIdx.y;
    const float* __restrict__ Pb = P + ((size_t)b * NN + kt * 64) * DD;

#pragma unroll
    for (int l = 0; l < 16; l++) {
        int idx = l * 256 + tid;
        int k   = idx >> 6;
        int d2  = idx & 63;
        float2 v = *(const float2*)(Pb + (size_t)k * DD + 2 * d2);
        uint16_t h0, l0, h1, l1;
        bsplit(v.x, h0, l0); bsplit(v.y, h1, l1);
        sH16[2 * d2][k]     = h0; sL16[2 * d2][k]     = l0;
        sH16[2 * d2 + 1][k] = h1; sL16[2 * d2 + 1][k] = l1;
    }
    __syncthreads();
#pragma unroll
    for (int l = 0; l < 32; l++) {
        int idx = l * 256 + tid;
        int pa  = idx >> 12;
        int rem = idx & 4095;
        int d   = rem >> 5;
        int kp  = rem & 31;
        const uint16_t* s = pa ? &sL16[d][0] : &sH16[d][0];
        g_Pt[(((size_t)b * 2 + pa) * DD + d) * (NN / 2) + kt * 32 + kp] =
            pk(s[2 * kp], s[2 * kp + 1]);
    }
}

// ============================================================
// kW: weight split (both W1 and W2 in one launch)
// ============================================================
__global__ __launch_bounds__(256) void kW_split(const float* __restrict__ W1,
                                                const float* __restrict__ W2)
{
    int bx = blockIdx.x;
    const float* W;
    uint32_t* dst;
    int OC, base;
    if (bx < 128) { W = W1; dst = g_W1s; OC = C1; base = bx; }
    else          { W = W2; dst = g_W2s; OC = C2; base = bx - 128; }
    int idx = base * 256 + threadIdx.x;
    int o   = idx >> 7;
    int kp  = idx & 127;
    if (o >= OC) return;
    float2 v = *(const float2*)(W + (size_t)o * C1 + 2 * kp);
    uint16_t h0, l0, h1, l1;
    bsplit(v.x, h0, l0); bsplit(v.y, h1, l1);
    dst[(size_t)o * 128 + kp]                    = pk(h0, h1);
    dst[(size_t)OC * 128 + (size_t)o * 128 + kp] = pk(l0, l1);
}

// ============================================================
// K1: conversion moved AFTER compute (tensor overlap); only STS between
//   barriers.  grid (8, MB); 3-stage shB cp.async ring; forced 2 CTAs/SM.
// ============================================================
__global__ __launch_bounds__(256, 2) void k1_mma(
    const float* __restrict__ E0, const float* __restrict__ E1)
{
    extern __shared__ uint32_t dyn[];
    __shared__ float sRow[128];
    __shared__ float sInv[128];

    const int tid  = threadIdx.x;
    const int lane = tid & 31;
    const int wid  = tid >> 5;
    const int wr   = wid & 1;
    const int wc   = wid >> 1;
    const int b    = blockIdx.y;
    const int ez   = blockIdx.x & 1;
    const int row0 = (blockIdx.x >> 1) * 128;
    const float* __restrict__ E = (ez ? E1 : E0) + (size_t)b * NN * NN;
    const uint32_t* __restrict__ Pt = g_Pt + (size_t)b * 2 * DD * (NN / 2);
    const uint32_t aA = smem_u32(dyn);            // shA: 2 planes
    const uint32_t bB = aA + 2 * PLANE;           // shB: 3-stage ring x 2 planes

    float acc[4][4][4];
#pragma unroll
    for (int i = 0; i < 4; i++)
#pragma unroll
        for (int j = 0; j < 4; j++)
#pragma unroll
            for (int k = 0; k < 4; k++) acc[i][j][k] = 0.f;

    const int q4 = (tid & 7) * 4;
    const int kp = (tid & 7) * 2;
    int rl[4];
#pragma unroll
    for (int l = 0; l < 4; l++) rl[l] = l * 32 + (tid >> 3);
    float rs[4] = {0.f, 0.f, 0.f, 0.f};

    float4 ev[4];
    uint2 hiw[4], low[4];

    // prologue: load + convert it0 into registers
#pragma unroll
    for (int l = 0; l < 4; l++)
        ev[l] = *(const float4*)(E + (size_t)(row0 + rl[l]) * NN + q4);
#pragma unroll
    for (int l = 0; l < 4; l++) {
        int grow = row0 + rl[l];
        int gk   = q4;
        float4 v = ev[l];
        if (grow == gk)     v.x = 0.f;
        if (grow == gk + 1) v.y = 0.f;
        if (grow == gk + 2) v.z = 0.f;
        if (grow == gk + 3) v.w = 0.f;
        rs[l] += (v.x + v.y) + (v.z + v.w);
        uint16_t h0, l0, h1, l1, h2, l2, h3, l3;
        bsplit(v.x, h0, l0); bsplit(v.y, h1, l1);
        bsplit(v.z, h2, l2); bsplit(v.w, h3, l3);
        hiw[l] = { pk(h0, h1), pk(h2, h3) };
        low[l] = { pk(l0, l1), pk(l2, l3) };
    }

    // cp.async stages 0 and 1
#pragma unroll
    for (int st = 0; st < 2; st++) {
#pragma unroll
        for (int l = 0; l < 4; l++) {
            int idx = l * 256 + tid;
            int pb = idx >> 9, rem = idx & 511, n = rem >> 2, c4 = (rem & 3) * 4;
            cpasync16(bB + st * 2 * PLANE + ((pb * 128 + n) * 20 + c4) * 4,
                      Pt + ((size_t)pb * DD + n) * (NN / 2) + st * 16 + c4);
        }
        CP_COMMIT();
    }

    for (int it = 0; it < 16; it++) {
        const int cur = it % 3;
        CP_WAIT1();
        __syncthreads();

        // STS only (8 STS.64 per thread) — tiny inter-barrier section
#pragma unroll
        for (int l = 0; l < 4; l++) {
            *(uint2*)(dyn + (size_t)0 * 2560 + rl[l] * 20 + kp) = hiw[l];
            *(uint2*)(dyn + (size_t)1 * 2560 + rl[l] * 20 + kp) = low[l];
        }
        if (it < 15) {
#pragma unroll
            for (int l = 0; l < 4; l++)
                ev[l] = *(const float4*)(E + (size_t)(row0 + rl[l]) * NN
                                         + (it + 1) * 32 + q4);
        }
        __syncthreads();

        if (it < 14) {
            const int st = (it + 2) % 3;
            const int kh = (it + 2) * 16;
#pragma unroll
            for (int l = 0; l < 4; l++) {
                int idx = l * 256 + tid;
                int pb = idx >> 9, rem = idx & 511, n = rem >> 2, c4 = (rem & 3) * 4;
                cpasync16(bB + st * 2 * PLANE + ((pb * 128 + n) * 20 + c4) * 4,
                          Pt + ((size_t)pb * DD + n) * (NN / 2) + kh + c4);
            }
            CP_COMMIT();
        } else {
            CP_COMMIT();
        }
        compute_chunk(aA, bB + cur * 2 * PLANE, acc, wr, wc, lane);

        // convert next iter's E AFTER compute (overlaps tensor drain / other CTA)
        if (it < 15) {
            const int k0n = (it + 1) * 32;
#pragma unroll
            for (int l = 0; l < 4; l++) {
                int grow = row0 + rl[l];
                int gk   = k0n + q4;
                float4 v = ev[l];
                if (grow == gk)     v.x = 0.f;
                if (grow == gk + 1) v.y = 0.f;
                if (grow == gk + 2) v.z = 0.f;
                if (grow == gk + 3) v.w = 0.f;
                rs[l] += (v.x + v.y) + (v.z + v.w);
                uint16_t h0, l0, h1, l1, h2, l2, h3, l3;
                bsplit(v.x, h0, l0); bsplit(v.y, h1, l1);
                bsplit(v.z, h2, l2); bsplit(v.w, h3, l3);
                hiw[l] = { pk(h0, h1), pk(h2, h3) };
                low[l] = { pk(l0, l1), pk(l2, l3) };
            }
        }
    }

#pragma unroll
    for (int l = 0; l < 4; l++) {
        float v = rs[l];
        v += __shfl_down_sync(0xffffffffu, v, 4);
        v += __shfl_down_sync(0xffffffffu, v, 2);
        v += __shfl_down_sync(0xffffffffu, v, 1);
        if ((tid & 7) == 0) sRow[rl[l]] = v;
    }
    __syncthreads();
    if (tid < 128) sInv[tid] = 1.0f / fmaxf(sRow[tid], 1e-12f);
    __syncthreads();

#pragma unroll
    for (int mf = 0; mf < 4; mf++) {
        int rll = wr * 64 + mf * 16 + (lane >> 2);
#pragma unroll
        for (int nf = 0; nf < 4; nf++) {
            int kpo = ez * 64 + wc * 16 + nf * 4 + (lane & 3);
            float i0 = sInv[rll], i1 = sInv[rll + 8];
            size_t m0r = (size_t)b * NN + row0 + rll;
            size_t m1r = m0r + 8;
            uint16_t h0, l0, h1, l1;
            bsplit(acc[mf][nf][0] * i0, h0, l0);
            bsplit(acc[mf][nf][1] * i0, h1, l1);
            g_Xs[m0r * 128 + kpo]                      = pk(h0, h1);
            g_Xs[(size_t)MTOT * 128 + m0r * 128 + kpo] = pk(l0, l1);
            bsplit(acc[mf][nf][2] * i1, h0, l0);
            bsplit(acc[mf][nf][3] * i1, h1, l1);
            g_Xs[m1r * 128 + kpo]                      = pk(h0, h1);
            g_Xs[(size_t)MTOT * 128 + m1r * 128 + kpo] = pk(l0, l1);
        }
    }
}

// ============================================================
// GEMM1: grid (MTOT/128, 2); cp.asyncs INTERLEAVED between MMA passes;
//   fused BN1 stats epilogue.
// ============================================================
__global__ __launch_bounds__(256) void k_gemm1(void)
{
    extern __shared__ uint32_t dyn[];
    __shared__ float sPS[128 * 17], sPQ[128 * 17];

    const int tid  = threadIdx.x;
    const int lane = tid & 31;
    const int wid  = tid >> 5;
    const int wr   = wid & 1;
    const int wc   = wid >> 1;
    const size_t m0 = (size_t)blockIdx.x * 128;
    const int    o0 = blockIdx.y * 128;
    const uint32_t bA  = smem_u32(dyn);
    const uint32_t bBs = bA + 4 * PLANE;

    const int l7  = lane & 7;
    const int tb0 = (lane >> 3) & 1;
    const int tb1 = (lane >> 4) & 1;

    float acc[4][4][4];
#pragma unroll
    for (int i = 0; i < 4; i++)
#pragma unroll
        for (int j = 0; j < 4; j++)
#pragma unroll
            for (int k = 0; k < 4; k++) acc[i][j][k] = 0.f;

#pragma unroll
    for (int l = 0; l < 4; l++) {
        int idx = l * 256 + tid;
        int pa = idx >> 9, rem = idx & 511, r = rem >> 2, c4 = (rem & 3) * 4;
        cpasync16(bA + ((pa * 128 + r) * 20 + c4) * 4,
                  g_Xs + (size_t)pa * MTOT * 128 + (m0 + r) * 128 + c4);
        cpasync16(bBs + ((pa * 128 + r) * 20 + c4) * 4,
                  g_W1s + (size_t)pa * C1 * 128 + (size_t)(o0 + r) * 128 + c4);
    }
    CP_COMMIT();

    for (int it = 0; it < 8; it++) {
        const int cur = it & 1;
        const bool pf = (it < 7);
        const int kh = (it + 1) * 16;
        const uint32_t aT = bA + cur * 2 * PLANE;
        const uint32_t bT = bBs + cur * 2 * PLANE;
        const uint32_t aN = bA + (1 - cur) * 2 * PLANE;
        const uint32_t bN = bBs + (1 - cur) * 2 * PLANE;
        CP_WAIT0();
        __syncthreads();

#pragma unroll
        for (int ks = 0; ks < 2; ks++) {
            uint32_t ah[4][4], al[4][4], bh[2][4], bl[2][4];
#pragma unroll
            for (int mf = 0; mf < 4; mf++) {
                uint32_t off = ((uint32_t)(wr * 64 + mf * 16 + tb0 * 8 + l7) * 20
                                + (uint32_t)(ks * 8 + tb1 * 4)) * 4;
                ldsm4(ah[mf][0], ah[mf][1], ah[mf][2], ah[mf][3], aT + off);
                ldsm4(al[mf][0], al[mf][1], al[mf][2], al[mf][3], aT + PLANE + off);
            }
#pragma unroll
            for (int np = 0; np < 2; np++) {
                uint32_t off = ((uint32_t)(wc * 32 + np * 16 + tb1 * 8 + l7) * 20
                                + (uint32_t)(ks * 8 + tb0 * 4)) * 4;
                ldsm4(bh[np][0], bh[np][1], bh[np][2], bh[np][3], bT + off);
                ldsm4(bl[np][0], bl[np][1], bl[np][2], bl[np][3], bT + PLANE + off);
            }
            pass16(acc, ah, bh);
            if (pf) {
#pragma unroll
                for (int l = ks * 2; l < ks * 2 + 1; l++) {
                    int idx = l * 256 + tid;
                    int pa = idx >> 9, rem = idx & 511, r = rem >> 2, c4 = (rem & 3) * 4;
                    cpasync16(aN + ((pa * 128 + r) * 20 + c4) * 4,
                              g_Xs + (size_t)pa * MTOT * 128 + (m0 + r) * 128 + kh + c4);
                    cpasync16(bN + ((pa * 128 + r) * 20 + c4) * 4,
                              g_W1s + (size_t)pa * C1 * 128 + (size_t)(o0 + r) * 128 + kh + c4);
                }
            }
            pass16(acc, ah, bl);
            if (pf) {
#pragma unroll
                for (int l = ks * 2 + 1; l < ks * 2 + 2; l++) {
                    int idx = l * 256 + tid;
                    int pa = idx >> 9, rem = idx & 511, r = rem >> 2, c4 = (rem & 3) * 4;
                    cpasync16(aN + ((pa * 128 + r) * 20 + c4) * 4,
                              g_Xs + (size_t)pa * MTOT * 128 + (m0 + r) * 128 + kh + c4);
                    cpasync16(bN + ((pa * 128 + r) * 20 + c4) * 4,
                              g_W1s + (size_t)pa * C1 * 128 + (size_t)(o0 + r) * 128 + kh + c4);
                }
            }
            pass16(acc, al, bh);
        }
        CP_COMMIT();
    }

#pragma unroll
    for (int mf = 0; mf < 4; mf++) {
        int rl = wr * 64 + mf * 16 + (lane >> 2);
#pragma unroll
        for (int nf = 0; nf < 4; nf++) {
            int col = o0 + wc * 32 + nf * 8 + (lane & 3) * 2;
            float* d0 = g_Y1 + (m0 + rl) * C1 + col;
            float* d1 = g_Y1 + (m0 + rl + 8) * C1 + col;
            *(float2*)d0 = { acc[mf][nf][0], acc[mf][nf][1] };
            *(float2*)d1 = { acc[mf][nf][2], acc[mf][nf][3] };
        }
    }
    __syncthreads();
    stats_epilogue(acc, wr, wc, lane, tid, sPS, sPQ, o0, blockIdx.x);
}

// ============================================================
// GEMM2: A = bn1+lrelu(g_Y1), conversion pipelined into shA[nxt];
//   1 barrier/iter; fused BN2 stats epilogue  (unchanged from R15)
// ============================================================
__global__ __launch_bounds__(256) void k_gemm2(float* __restrict__ out)
{
    extern __shared__ uint32_t dyn[];
    __shared__ float sBNa[C1], sBNc[C1];
    __shared__ float sPS[128 * 17], sPQ[128 * 17];

    const int tid  = threadIdx.x;
    const int lane = tid & 31;
    const int wid  = tid >> 5;
    const int wr   = wid & 1;
    const int wc   = wid >> 1;
    const size_t m0 = (size_t)blockIdx.x * 128;
    const uint32_t aA  = smem_u32(dyn);
    const uint32_t bBs = aA + 4 * PLANE;

    sBNa[tid] = g_ab[tid];
    sBNc[tid] = g_ab[C1 + tid];
    __syncthreads();

    float acc[4][4][4];
#pragma unroll
    for (int i = 0; i < 4; i++)
#pragma unroll
        for (int j = 0; j < 4; j++)
#pragma unroll
            for (int k = 0; k < 4; k++) acc[i][j][k] = 0.f;

    float2 ev[8];
#pragma unroll
    for (int l = 0; l < 8; l++) {
        int idx = l * 256 + tid;
        int r = idx >> 4, kp2 = idx & 15;
        ev[l] = *(const float2*)(g_Y1 + (m0 + r) * C1 + 2 * kp2);
    }
    {
        uint32_t (*pA)[128][20] = (uint32_t(*)[128][20])dyn;
#pragma unroll
        for (int l = 0; l < 8; l++) {
            int idx = l * 256 + tid;
            int r = idx >> 4, kp2 = idx & 15;
            int ch = 2 * kp2;
            float2 v = ev[l];
            v.x = lrelu(fmaf(sBNa[ch],     v.x, sBNc[ch]));
            v.y = lrelu(fmaf(sBNa[ch + 1], v.y, sBNc[ch + 1]));
            uint16_t h0, l0, h1, l1;
            bsplit(v.x, h0, l0); bsplit(v.y, h1, l1);
            pA[0][r][kp2] = pk(h0, h1);
            pA[1][r][kp2] = pk(l0, l1);
        }
    }
#pragma unroll
    for (int l = 0; l < 8; l++) {
        int idx = l * 256 + tid;
        int r = idx >> 4, kp2 = idx & 15;
        ev[l] = *(const float2*)(g_Y1 + (m0 + r) * C1 + 32 + 2 * kp2);
    }
#pragma unroll
    for (int l = 0; l < 4; l++) {
        int idx = l * 256 + tid;
        int pb = idx >> 9, rem = idx & 511, n = rem >> 2, c4 = (rem & 3) * 4;
        cpasync16(bBs + ((pb * 128 + n) * 20 + c4) * 4,
                  g_W2s + (size_t)pb * C2 * 128 + (size_t)n * 128 + c4);
    }
    CP_COMMIT();
    CP_WAIT0();
    __syncthreads();

    for (int it = 0; it < 8; it++) {
        const int cur = it & 1;
        const int nxt = cur ^ 1;
        if (it < 7) {
            const int kh = (it + 1) * 16;
#pragma unroll
            for (int l = 0; l < 4; l++) {
                int idx = l * 256 + tid;
                int pb = idx >> 9, rem = idx & 511, n = rem >> 2, c4 = (rem & 3) * 4;
                cpasync16(bBs + nxt * 2 * PLANE + ((pb * 128 + n) * 20 + c4) * 4,
                          g_W2s + (size_t)pb * C2 * 128 + (size_t)n * 128 + kh + c4);
            }
            CP_COMMIT();
        }
        compute_chunk(aA + cur * 2 * PLANE, bBs + cur * 2 * PLANE, acc, wr, wc, lane);
        if (it < 7) {
            uint32_t (*pA)[128][20] = ((uint32_t(*)[128][20])dyn) + nxt * 2;
            const int k0 = (it + 1) * 32;
#pragma unroll
            for (int l = 0; l < 8; l++) {
                int idx = l * 256 + tid;
                int r = idx >> 4, kp2 = idx & 15;
                int ch = k0 + 2 * kp2;
                float2 v = ev[l];
                v.x = lrelu(fmaf(sBNa[ch],     v.x, sBNc[ch]));
                v.y = lrelu(fmaf(sBNa[ch + 1], v.y, sBNc[ch + 1]));
                uint16_t h0, l0, h1, l1;
                bsplit(v.x, h0, l0); bsplit(v.y, h1, l1);
                pA[0][r][kp2] = pk(h0, h1);
                pA[1][r][kp2] = pk(l0, l1);
            }
        }
        if (it < 6) {
#pragma unroll
            for (int l = 0; l < 8; l++) {
                int idx = l * 256 + tid;
                int r = idx >> 4, kp2 = idx & 15;
                ev[l] = *(const float2*)(g_Y1 + (m0 + r) * C1 + (it + 2) * 32 + 2 * kp2);
            }
        }
        if (it < 7) { CP_WAIT0(); __syncthreads(); }
    }

#pragma unroll
    for (int mf = 0; mf < 4; mf++) {
        int rl = wr * 64 + mf * 16 + (lane >> 2);
#pragma unroll
        for (int nf = 0; nf < 4; nf++) {
            int col = wc * 32 + nf * 8 + (lane & 3) * 2;
            float* d0 = out + (m0 + rl) * C2 + col;
            float* d1 = out + (m0 + rl + 8) * C2 + col;
            *(float2*)d0 = { acc[mf][nf][0], acc[mf][nf][1] };
            *(float2*)d1 = { acc[mf][nf][2], acc[mf][nf][3] };
        }
    }
    __syncthreads();
    stats_epilogue(acc, wr, wc, lane, tid, sPS, sPQ, 0, blockIdx.x);
}

// ============================================================
// finalize: one block per channel, reduce 1024 float partials in fp64
// ============================================================
template <int C>
__global__ __launch_bounds__(256) void k_finalizeF(
    const float* __restrict__ g, const float* __restrict__ bb, int aoff)
{
    __shared__ double ss[256], sq[256];
    const int c   = blockIdx.x;
    const int tid = threadIdx.x;
    double s = 0.0, q = 0.0;
    for (int i = tid; i < 1024; i += 256) {
        s += (double)g_partS[(size_t)c * 1024 + i];
        q += (double)g_partQ[(size_t)c * 1024 + i];
    }
    ss[tid] = s; sq[tid] = q;
    __syncthreads();
    for (int off = 128; off > 0; off >>= 1) {
        if (tid < off) { ss[tid] += ss[tid + off]; sq[tid] += sq[tid + off]; }
        __syncthreads();
    }
    if (tid == 0) {
        const double invM = 1.0 / (double)MTOT;
        double mean = ss[0] * invM;
        double var  = sq[0] * invM - mean * mean;
        float a = (float)((double)g[c] / sqrt(var + 1e-5));
        g_ab[aoff + c]     = a;
        g_ab[aoff + C + c] = (float)((double)bb[c] - mean * (double)a);
    }
}

__global__ __launch_bounds__(256) void k_bn_act2(float* __restrict__ Y)
{
    size_t i4 = (size_t)blockIdx.x * blockDim.x + threadIdx.x;
    int c4 = (int)(i4 & (C2 / 4 - 1)) * 4;
    float4 v  = ((float4*)Y)[i4];
    float4 av = *(const float4*)&g_ab[2 * C1 + c4];
    float4 cv = *(const float4*)&g_ab[2 * C1 + C2 + c4];
    v.x = lrelu(fmaf(av.x, v.x, cv.x));
    v.y = lrelu(fmaf(av.y, v.y, cv.y));
    v.z = lrelu(fmaf(av.z, v.z, cv.z));
    v.w = lrelu(fmaf(av.w, v.w, cv.w));
    ((float4*)Y)[i4] = v;
}

// ============================================================
extern "C" void kernel_launch(void* const* d_in, const int* in_sizes, int n_in,
                              void* d_out, int out_size)
{
    (void)in_sizes; (void)n_in; (void)out_size;
    const float* E0 = (const float*)d_in[0];
    const float* E1 = (const float*)d_in[1];
    const float* P  = (const float*)d_in[2];
    const float* W1 = (const float*)d_in[3];
    const float* g1 = (const float*)d_in[4];
    const float* b1 = (const float*)d_in[5];
    const float* W2 = (const float*)d_in[6];
    const float* g2 = (const float*)d_in[7];
    const float* b2 = (const float*)d_in[8];
    float* out = (float*)d_out;

    cudaFuncSetAttribute(k1_mma,  cudaFuncAttributeMaxDynamicSharedMemorySize, 81920);
    cudaFuncSetAttribute(k_gemm1, cudaFuncAttributeMaxDynamicSharedMemorySize, 81920);
    cudaFuncSetAttribute(k_gemm2, cudaFuncAttributeMaxDynamicSharedMemorySize, 81920);

    // 0. one-time conversions
    kW_split<<<192, 256>>>(W1, W2);
    kP_split<<<dim3(MB, 8), 256>>>(P);

    // 1. edge aggregation (conversion overlapped with tensor) -> g_Xs
    k1_mma<<<dim3(8, MB), 256, 81920>>>(E0, E1);

    // 2. GEMM1 (interleaved cp.async) + fused BN1 stats
    k_gemm1<<<dim3(MTOT / 128, 2), 256, 81920>>>();
    k_finalizeF<C1><<<C1, 256>>>(g1, b1, 0);

    // 3. GEMM2 (BN1+LReLU on load) + fused BN2 stats
    k_gemm2<<<dim3(MTOT / 128, 1), 256, 81920>>>(out);
    k_finalizeF<C2><<<C2, 256>>>(g2, b2, 2 * C1);

    // 4. in-place BN2 + LReLU
    k_bn_act2<<<16384, 256>>>(out);
}

// round 17
// speedup vs baseline: 1.1443x; 1.1443x over previous
#include <cuda_runtime.h>
#include <cuda_bf16.h>
#include <cstdint>

// Problem constants
#define MB   256
#define NN   512
#define DD   128
#define C1   256
#define C2   128
#define MTOT (MB * NN)

// ---------------- scratch ----------------
__device__ uint32_t g_Pt[(size_t)MB * 2 * DD * (NN / 2)];
__device__ uint32_t g_Xs[2 * (size_t)MTOT * (C1 / 2)];
__device__ float    g_Y1[(size_t)MTOT * C1];
__device__ uint32_t g_W1s[2 * C1 * (C1 / 2)];
__device__ uint32_t g_W2s[2 * C2 * (C1 / 2)];
__device__ float    g_partS[256 * 1024];
__device__ float    g_partQ[256 * 1024];
__device__ float    g_ab[2 * C1 + 2 * C2];

__device__ __forceinline__ float lrelu(float y) { return y >= 0.f ? y : 0.01f * y; }

// ---------------- helpers ----------------
__device__ __forceinline__ void bsplit(float x, uint16_t& h, uint16_t& l) {
    __nv_bfloat16 hb = __float2bfloat16(x);
    float r = x - __bfloat162float(hb);
    __nv_bfloat16 lb = __float2bfloat16(r);
    h = __bfloat16_as_ushort(hb);
    l = __bfloat16_as_ushort(lb);
}
__device__ __forceinline__ uint32_t pk(uint16_t a, uint16_t b) {
    return (uint32_t)a | ((uint32_t)b << 16);
}
__device__ __forceinline__ uint32_t smem_u32(const void* p) {
    uint32_t a;
    asm("{ .reg .u64 t; cvta.to.shared.u64 t, %1; cvt.u32.u64 %0, t; }" : "=r"(a) : "l"(p));
    return a;
}
__device__ __forceinline__ void cpasync16(uint32_t saddr, const void* g) {
    asm volatile("cp.async.cg.shared.global [%0], [%1], 16;" :: "r"(saddr), "l"(g));
}
#define CP_COMMIT() asm volatile("cp.async.commit_group;" ::: "memory")
#define CP_WAIT0()  asm volatile("cp.async.wait_group 0;" ::: "memory")
#define CP_WAIT1()  asm volatile("cp.async.wait_group 1;" ::: "memory")

__device__ __forceinline__ void mma16816(float* c, const uint32_t* a, const uint32_t* b) {
    asm volatile(
        "mma.sync.aligned.m16n8k16.row.col.f32.bf16.bf16.f32 "
        "{%0,%1,%2,%3}, {%4,%5,%6,%7}, {%8,%9}, {%0,%1,%2,%3};"
        : "+f"(c[0]), "+f"(c[1]), "+f"(c[2]), "+f"(c[3])
        : "r"(a[0]), "r"(a[1]), "r"(a[2]), "r"(a[3]), "r"(b[0]), "r"(b[1]));
}
__device__ __forceinline__ void ldsm4(uint32_t& r0, uint32_t& r1, uint32_t& r2,
                                      uint32_t& r3, uint32_t a) {
    asm volatile("ldmatrix.sync.aligned.m8n8.x4.shared.b16 {%0,%1,%2,%3}, [%4];"
        : "=r"(r0), "=r"(r1), "=r"(r2), "=r"(r3) : "r"(a));
}

// ---------------- warp-tile compute over one 32-k chunk (ldmatrix) ----------
#define PLANE 10240u            // bytes per [128][20] u32 plane
__device__ __forceinline__ void compute_chunk(
    uint32_t aB, uint32_t bB, float acc[4][4][4], int wr, int wc, int lane)
{
    const int l7  = lane & 7;
    const int tb0 = (lane >> 3) & 1;
    const int tb1 = (lane >> 4) & 1;
#pragma unroll
    for (int ks = 0; ks < 2; ks++) {
        uint32_t ah[4][4], al[4][4], bh[2][4], bl[2][4];
#pragma unroll
        for (int mf = 0; mf < 4; mf++) {
            uint32_t off = ((uint32_t)(wr * 64 + mf * 16 + tb0 * 8 + l7) * 20
                            + (uint32_t)(ks * 8 + tb1 * 4)) * 4;
            ldsm4(ah[mf][0], ah[mf][1], ah[mf][2], ah[mf][3], aB + off);
            ldsm4(al[mf][0], al[mf][1], al[mf][2], al[mf][3], aB + PLANE + off);
        }
#pragma unroll
        for (int np = 0; np < 2; np++) {
            uint32_t off = ((uint32_t)(wc * 32 + np * 16 + tb1 * 8 + l7) * 20
                            + (uint32_t)(ks * 8 + tb0 * 4)) * 4;
            ldsm4(bh[np][0], bh[np][1], bh[np][2], bh[np][3], bB + off);
            ldsm4(bl[np][0], bl[np][1], bl[np][2], bl[np][3], bB + PLANE + off);
        }
#pragma unroll
        for (int mf = 0; mf < 4; mf++)
#pragma unroll
            for (int nf = 0; nf < 4; nf++)
                mma16816(acc[mf][nf], ah[mf], &bh[nf >> 1][(nf & 1) * 2]);
#pragma unroll
        for (int mf = 0; mf < 4; mf++)
#pragma unroll
            for (int nf = 0; nf < 4; nf++)
                mma16816(acc[mf][nf], ah[mf], &bl[nf >> 1][(nf & 1) * 2]);
#pragma unroll
        for (int mf = 0; mf < 4; mf++)
#pragma unroll
            for (int nf = 0; nf < 4; nf++)
                mma16816(acc[mf][nf], al[mf], &bh[nf >> 1][(nf & 1) * 2]);
    }
}

// ---------------- fused per-CTA BN stats epilogue (deterministic) ----------
__device__ __forceinline__ void stats_epilogue(
    const float acc[4][4][4], int wr, int wc, int lane, int tid,
    float* sPS, float* sPQ, int chBase, int bx)
{
    const int ci = wr * 8 + (lane >> 2);
#pragma unroll
    for (int nf = 0; nf < 4; nf++)
#pragma unroll
        for (int c01 = 0; c01 < 2; c01++) {
            int col = wc * 32 + nf * 8 + (lane & 3) * 2 + c01;
            float s = 0.f, q = 0.f;
#pragma unroll
            for (int mf = 0; mf < 4; mf++) {
                float y0 = acc[mf][nf][c01];
                float y1 = acc[mf][nf][2 + c01];
                s += y0 + y1;
                q += y0 * y0 + y1 * y1;
            }
            sPS[col * 17 + ci] = s;
            sPQ[col * 17 + ci] = q;
        }
    __syncthreads();
    if (tid < 128) {
        float s = 0.f, q = 0.f;
#pragma unroll
        for (int i = 0; i < 16; i++) {
            s += sPS[tid * 17 + i];
            q += sPQ[tid * 17 + i];
        }
        g_partS[(size_t)(chBase + tid) * 1024 + bx] = s;
        g_partQ[(size_t)(chBase + tid) * 1024 + bx] = q;
    }
}

// ============================================================
// kP: P -> transposed split planes g_Pt[b][pa][d][kp]
// ============================================================
__global__ __launch_bounds__(256) void kP_split(const float* __restrict__ P)
{
    __shared__ uint16_t sH16[128][66];
    __shared__ uint16_t sL16[128][66];

    const int tid = threadIdx.x;
    const int b   = blockIdx.x;
    const int kt  = blockIdx.y;
    const float* __restrict__ Pb = P + ((size_t)b * NN + kt * 64) * DD;

#pragma unroll
    for (int l = 0; l < 16; l++) {
        int idx = l * 256 + tid;
        int k   = idx >> 6;
        int d2  = idx & 63;
        float2 v = *(const float2*)(Pb + (size_t)k * DD + 2 * d2);
        uint16_t h0, l0, h1, l1;
        bsplit(v.x, h0, l0); bsplit(v.y, h1, l1);
        sH16[2 * d2][k]     = h0; sL16[2 * d2][k]     = l0;
        sH16[2 * d2 + 1][k] = h1; sL16[2 * d2 + 1][k] = l1;
    }
    __syncthreads();
#pragma unroll
    for (int l = 0; l < 32; l++) {
        int idx = l * 256 + tid;
        int pa  = idx >> 12;
        int rem = idx & 4095;
        int d   = rem >> 5;
        int kp  = rem & 31;
        const uint16_t* s = pa ? &sL16[d][0] : &sH16[d][0];
        g_Pt[(((size_t)b * 2 + pa) * DD + d) * (NN / 2) + kt * 32 + kp] =
            pk(s[2 * kp], s[2 * kp + 1]);
    }
}

// ============================================================
// kW: weight split (both W1 and W2 in one launch)
//   blocks [0,128): W1 (o,kp); blocks [128,192): W2
// ============================================================
__global__ __launch_bounds__(256) void kW_split(const float* __restrict__ W1,
                                                const float* __restrict__ W2)
{
    int bx = blockIdx.x;
    const float* W;
    uint32_t* dst;
    int OC, base;
    if (bx < 128) { W = W1; dst = g_W1s; OC = C1; base = bx; }
    else          { W = W2; dst = g_W2s; OC = C2; base = bx - 128; }
    int idx = base * 256 + threadIdx.x;
    int o   = idx >> 7;
    int kp  = idx & 127;
    if (o >= OC) return;
    float2 v = *(const float2*)(W + (size_t)o * C1 + 2 * kp);
    uint16_t h0, l0, h1, l1;
    bsplit(v.x, h0, l0); bsplit(v.y, h1, l1);
    dst[(size_t)o * 128 + kp]                    = pk(h0, h1);
    dst[(size_t)OC * 128 + (size_t)o * 128 + kp] = pk(l0, l1);
}

// ============================================================
// K1: grid (8, MB) — batch-local CTA order (time-neutral, lower DRAM).
//   Single-buffered shA (STS.64 conversion), 3-stage shB cp.async ring.
// ============================================================
__global__ __launch_bounds__(256) void k1_mma(
    const float* __restrict__ E0, const float* __restrict__ E1)
{
    extern __shared__ uint32_t dyn[];
    __shared__ float sRow[128];
    __shared__ float sInv[128];

    const int tid  = threadIdx.x;
    const int lane = tid & 31;
    const int wid  = tid >> 5;
    const int wr   = wid & 1;
    const int wc   = wid >> 1;
    const int b    = blockIdx.y;
    const int ez   = blockIdx.x & 1;
    const int row0 = (blockIdx.x >> 1) * 128;
    const float* __restrict__ E = (ez ? E1 : E0) + (size_t)b * NN * NN;
    const uint32_t* __restrict__ Pt = g_Pt + (size_t)b * 2 * DD * (NN / 2);
    const uint32_t aA = smem_u32(dyn);            // shA: 2 planes
    const uint32_t bB = aA + 2 * PLANE;           // shB: 3-stage ring x 2 planes

    float acc[4][4][4];
#pragma unroll
    for (int i = 0; i < 4; i++)
#pragma unroll
        for (int j = 0; j < 4; j++)
#pragma unroll
            for (int k = 0; k < 4; k++) acc[i][j][k] = 0.f;

    const int q4 = (tid & 7) * 4;
    int rl[4];
#pragma unroll
    for (int l = 0; l < 4; l++) rl[l] = l * 32 + (tid >> 3);
    float rs[4] = {0.f, 0.f, 0.f, 0.f};

    float4 ev[4];
#pragma unroll
    for (int l = 0; l < 4; l++)
        ev[l] = *(const float4*)(E + (size_t)(row0 + rl[l]) * NN + q4);
#pragma unroll
    for (int st = 0; st < 2; st++) {
#pragma unroll
        for (int l = 0; l < 4; l++) {
            int idx = l * 256 + tid;
            int pb = idx >> 9, rem = idx & 511, n = rem >> 2, c4 = (rem & 3) * 4;
            cpasync16(bB + st * 2 * PLANE + ((pb * 128 + n) * 20 + c4) * 4,
                      Pt + ((size_t)pb * DD + n) * (NN / 2) + st * 16 + c4);
        }
        CP_COMMIT();
    }

    for (int it = 0; it < 16; it++) {
        const int k0  = it * 32;
        const int cur = it % 3;
        CP_WAIT1();
        __syncthreads();

#pragma unroll
        for (int l = 0; l < 4; l++) {
            int grow = row0 + rl[l];
            int gk   = k0 + q4;
            float4 v = ev[l];
            if (grow == gk)     v.x = 0.f;
            if (grow == gk + 1) v.y = 0.f;
            if (grow == gk + 2) v.z = 0.f;
            if (grow == gk + 3) v.w = 0.f;
            rs[l] += (v.x + v.y) + (v.z + v.w);
            uint16_t h0, l0, h1, l1, h2, l2, h3, l3;
            bsplit(v.x, h0, l0); bsplit(v.y, h1, l1);
            bsplit(v.z, h2, l2); bsplit(v.w, h3, l3);
            int kp = (tid & 7) * 2;
            uint2 hiw = { pk(h0, h1), pk(h2, h3) };
            uint2 low = { pk(l0, l1), pk(l2, l3) };
            *(uint2*)(dyn + (size_t)0 * 2560 + rl[l] * 20 + kp) = hiw;
            *(uint2*)(dyn + (size_t)1 * 2560 + rl[l] * 20 + kp) = low;
        }
        if (it < 15) {
#pragma unroll
            for (int l = 0; l < 4; l++)
                ev[l] = *(const float4*)(E + (size_t)(row0 + rl[l]) * NN + k0 + 32 + q4);
        }
        __syncthreads();

        if (it < 14) {
            const int st = (it + 2) % 3;
            const int kh = (it + 2) * 16;
#pragma unroll
            for (int l = 0; l < 4; l++) {
                int idx = l * 256 + tid;
                int pb = idx >> 9, rem = idx & 511, n = rem >> 2, c4 = (rem & 3) * 4;
                cpasync16(bB + st * 2 * PLANE + ((pb * 128 + n) * 20 + c4) * 4,
                          Pt + ((size_t)pb * DD + n) * (NN / 2) + kh + c4);
            }
            CP_COMMIT();
        } else {
            CP_COMMIT();
        }
        compute_chunk(aA, bB + cur * 2 * PLANE, acc, wr, wc, lane);
    }

#pragma unroll
    for (int l = 0; l < 4; l++) {
        float v = rs[l];
        v += __shfl_down_sync(0xffffffffu, v, 4);
        v += __shfl_down_sync(0xffffffffu, v, 2);
        v += __shfl_down_sync(0xffffffffu, v, 1);
        if ((tid & 7) == 0) sRow[rl[l]] = v;
    }
    __syncthreads();
    if (tid < 128) sInv[tid] = 1.0f / fmaxf(sRow[tid], 1e-12f);
    __syncthreads();

#pragma unroll
    for (int mf = 0; mf < 4; mf++) {
        int rll = wr * 64 + mf * 16 + (lane >> 2);
#pragma unroll
        for (int nf = 0; nf < 4; nf++) {
            int kpo = ez * 64 + wc * 16 + nf * 4 + (lane & 3);
            float i0 = sInv[rll], i1 = sInv[rll + 8];
            size_t m0r = (size_t)b * NN + row0 + rll;
            size_t m1r = m0r + 8;
            uint16_t h0, l0, h1, l1;
            bsplit(acc[mf][nf][0] * i0, h0, l0);
            bsplit(acc[mf][nf][1] * i0, h1, l1);
            g_Xs[m0r * 128 + kpo]                      = pk(h0, h1);
            g_Xs[(size_t)MTOT * 128 + m0r * 128 + kpo] = pk(l0, l1);
            bsplit(acc[mf][nf][2] * i1, h0, l0);
            bsplit(acc[mf][nf][3] * i1, h1, l1);
            g_Xs[m1r * 128 + kpo]                      = pk(h0, h1);
            g_Xs[(size_t)MTOT * 128 + m1r * 128 + kpo] = pk(l0, l1);
        }
    }
}

// ============================================================
// GEMM1: grid (MTOT/128, 2) — R13 ordering (measured fastest).
//   Fully cp.async double-buffered + fused BN1 stats epilogue.
// ============================================================
__global__ __launch_bounds__(256) void k_gemm1(void)
{
    extern __shared__ uint32_t dyn[];
    __shared__ float sPS[128 * 17], sPQ[128 * 17];

    const int tid  = threadIdx.x;
    const int lane = tid & 31;
    const int wid  = tid >> 5;
    const int wr   = wid & 1;
    const int wc   = wid >> 1;
    const size_t m0 = (size_t)blockIdx.x * 128;
    const int    o0 = blockIdx.y * 128;
    const uint32_t bA  = smem_u32(dyn);
    const uint32_t bBs = bA + 4 * PLANE;

    float acc[4][4][4];
#pragma unroll
    for (int i = 0; i < 4; i++)
#pragma unroll
        for (int j = 0; j < 4; j++)
#pragma unroll
            for (int k = 0; k < 4; k++) acc[i][j][k] = 0.f;

#pragma unroll
    for (int l = 0; l < 4; l++) {
        int idx = l * 256 + tid;
        int pa = idx >> 9, rem = idx & 511, r = rem >> 2, c4 = (rem & 3) * 4;
        cpasync16(bA + ((pa * 128 + r) * 20 + c4) * 4,
                  g_Xs + (size_t)pa * MTOT * 128 + (m0 + r) * 128 + c4);
        cpasync16(bBs + ((pa * 128 + r) * 20 + c4) * 4,
                  g_W1s + (size_t)pa * C1 * 128 + (size_t)(o0 + r) * 128 + c4);
    }
    CP_COMMIT();

    for (int it = 0; it < 8; it++) {
        const int cur = it & 1;
        CP_WAIT0();
        __syncthreads();
        if (it < 7) {
            const int kh = (it + 1) * 16;
#pragma unroll
            for (int l = 0; l < 4; l++) {
                int idx = l * 256 + tid;
                int pa = idx >> 9, rem = idx & 511, r = rem >> 2, c4 = (rem & 3) * 4;
                cpasync16(bA + (1 - cur) * 2 * PLANE + ((pa * 128 + r) * 20 + c4) * 4,
                          g_Xs + (size_t)pa * MTOT * 128 + (m0 + r) * 128 + kh + c4);
                cpasync16(bBs + (1 - cur) * 2 * PLANE + ((pa * 128 + r) * 20 + c4) * 4,
                          g_W1s + (size_t)pa * C1 * 128 + (size_t)(o0 + r) * 128 + kh + c4);
            }
            CP_COMMIT();
        }
        compute_chunk(bA + cur * 2 * PLANE, bBs + cur * 2 * PLANE, acc, wr, wc, lane);
    }

#pragma unroll
    for (int mf = 0; mf < 4; mf++) {
        int rl = wr * 64 + mf * 16 + (lane >> 2);
#pragma unroll
        for (int nf = 0; nf < 4; nf++) {
            int col = o0 + wc * 32 + nf * 8 + (lane & 3) * 2;
            float* d0 = g_Y1 + (m0 + rl) * C1 + col;
            float* d1 = g_Y1 + (m0 + rl + 8) * C1 + col;
            *(float2*)d0 = { acc[mf][nf][0], acc[mf][nf][1] };
            *(float2*)d1 = { acc[mf][nf][2], acc[mf][nf][3] };
        }
    }
    __syncthreads();
    stats_epilogue(acc, wr, wc, lane, tid, sPS, sPQ, o0, blockIdx.x);
}

// ============================================================
// GEMM2: A = bn1+lrelu(g_Y1), conversion pipelined into shA[nxt];
//   1 barrier/iter; fused BN2 stats epilogue
// ============================================================
__global__ __launch_bounds__(256) void k_gemm2(float* __restrict__ out)
{
    extern __shared__ uint32_t dyn[];
    __shared__ float sBNa[C1], sBNc[C1];
    __shared__ float sPS[128 * 17], sPQ[128 * 17];

    const int tid  = threadIdx.x;
    const int lane = tid & 31;
    const int wid  = tid >> 5;
    const int wr   = wid & 1;
    const int wc   = wid >> 1;
    const size_t m0 = (size_t)blockIdx.x * 128;
    const uint32_t aA  = smem_u32(dyn);
    const uint32_t bBs = aA + 4 * PLANE;

    sBNa[tid] = g_ab[tid];
    sBNc[tid] = g_ab[C1 + tid];
    __syncthreads();

    float acc[4][4][4];
#pragma unroll
    for (int i = 0; i < 4; i++)
#pragma unroll
        for (int j = 0; j < 4; j++)
#pragma unroll
            for (int k = 0; k < 4; k++) acc[i][j][k] = 0.f;

    float2 ev[8];
#pragma unroll
    for (int l = 0; l < 8; l++) {
        int idx = l * 256 + tid;
        int r = idx >> 4, kp2 = idx & 15;
        ev[l] = *(const float2*)(g_Y1 + (m0 + r) * C1 + 2 * kp2);
    }
    {
        uint32_t (*pA)[128][20] = (uint32_t(*)[128][20])dyn;
#pragma unroll
        for (int l = 0; l < 8; l++) {
            int idx = l * 256 + tid;
            int r = idx >> 4, kp2 = idx & 15;
            int ch = 2 * kp2;
            float2 v = ev[l];
            v.x = lrelu(fmaf(sBNa[ch],     v.x, sBNc[ch]));
            v.y = lrelu(fmaf(sBNa[ch + 1], v.y, sBNc[ch + 1]));
            uint16_t h0, l0, h1, l1;
            bsplit(v.x, h0, l0); bsplit(v.y, h1, l1);
            pA[0][r][kp2] = pk(h0, h1);
            pA[1][r][kp2] = pk(l0, l1);
        }
    }
#pragma unroll
    for (int l = 0; l < 8; l++) {
        int idx = l * 256 + tid;
        int r = idx >> 4, kp2 = idx & 15;
        ev[l] = *(const float2*)(g_Y1 + (m0 + r) * C1 + 32 + 2 * kp2);
    }
#pragma unroll
    for (int l = 0; l < 4; l++) {
        int idx = l * 256 + tid;
        int pb = idx >> 9, rem = idx & 511, n = rem >> 2, c4 = (rem & 3) * 4;
        cpasync16(bBs + ((pb * 128 + n) * 20 + c4) * 4,
                  g_W2s + (size_t)pb * C2 * 128 + (size_t)n * 128 + c4);
    }
    CP_COMMIT();
    CP_WAIT0();
    __syncthreads();

    for (int it = 0; it < 8; it++) {
        const int cur = it & 1;
        const int nxt = cur ^ 1;
        if (it < 7) {
            const int kh = (it + 1) * 16;
#pragma unroll
            for (int l = 0; l < 4; l++) {
                int idx = l * 256 + tid;
                int pb = idx >> 9, rem = idx & 511, n = rem >> 2, c4 = (rem & 3) * 4;
                cpasync16(bBs + nxt * 2 * PLANE + ((pb * 128 + n) * 20 + c4) * 4,
                          g_W2s + (size_t)pb * C2 * 128 + (size_t)n * 128 + kh + c4);
            }
            CP_COMMIT();
        }
        compute_chunk(aA + cur * 2 * PLANE, bBs + cur * 2 * PLANE, acc, wr, wc, lane);
        if (it < 7) {
            uint32_t (*pA)[128][20] = ((uint32_t(*)[128][20])dyn) + nxt * 2;
            const int k0 = (it + 1) * 32;
#pragma unroll
            for (int l = 0; l < 8; l++) {
                int idx = l * 256 + tid;
                int r = idx >> 4, kp2 = idx & 15;
                int ch = k0 + 2 * kp2;
                float2 v = ev[l];
                v.x = lrelu(fmaf(sBNa[ch],     v.x, sBNc[ch]));
                v.y = lrelu(fmaf(sBNa[ch + 1], v.y, sBNc[ch + 1]));
                uint16_t h0, l0, h1, l1;
                bsplit(v.x, h0, l0); bsplit(v.y, h1, l1);
                pA[0][r][kp2] = pk(h0, h1);
                pA[1][r][kp2] = pk(l0, l1);
            }
        }
        if (it < 6) {
#pragma unroll
            for (int l = 0; l < 8; l++) {
                int idx = l * 256 + tid;
                int r = idx >> 4, kp2 = idx & 15;
                ev[l] = *(const float2*)(g_Y1 + (m0 + r) * C1 + (it + 2) * 32 + 2 * kp2);
            }
        }
        if (it < 7) { CP_WAIT0(); __syncthreads(); }
    }

#pragma unroll
    for (int mf = 0; mf < 4; mf++) {
        int rl = wr * 64 + mf * 16 + (lane >> 2);
#pragma unroll
        for (int nf = 0; nf < 4; nf++) {
            int col = wc * 32 + nf * 8 + (lane & 3) * 2;
            float* d0 = out + (m0 + rl) * C2 + col;
            float* d1 = out + (m0 + rl + 8) * C2 + col;
            *(float2*)d0 = { acc[mf][nf][0], acc[mf][nf][1] };
            *(float2*)d1 = { acc[mf][nf][2], acc[mf][nf][3] };
        }
    }
    __syncthreads();
    stats_epilogue(acc, wr, wc, lane, tid, sPS, sPQ, 0, blockIdx.x);
}

// ============================================================
// finalize: one block per channel, reduce 1024 float partials in fp64
// ============================================================
template <int C>
__global__ __launch_bounds__(256) void k_finalizeF(
    const float* __restrict__ g, const float* __restrict__ bb, int aoff)
{
    __shared__ double ss[256], sq[256];
    const int c   = blockIdx.x;
    const int tid = threadIdx.x;
    double s = 0.0, q = 0.0;
    for (int i = tid; i < 1024; i += 256) {
        s += (double)g_partS[(size_t)c * 1024 + i];
        q += (double)g_partQ[(size_t)c * 1024 + i];
    }
    ss[tid] = s; sq[tid] = q;
    __syncthreads();
    for (int off = 128; off > 0; off >>= 1) {
        if (tid < off) { ss[tid] += ss[tid + off]; sq[tid] += sq[tid + off]; }
        __syncthreads();
    }
    if (tid == 0) {
        const double invM = 1.0 / (double)MTOT;
        double mean = ss[0] * invM;
        double var  = sq[0] * invM - mean * mean;
        float a = (float)((double)g[c] / sqrt(var + 1e-5));
        g_ab[aoff + c]     = a;
        g_ab[aoff + C + c] = (float)((double)bb[c] - mean * (double)a);
    }
}

__global__ __launch_bounds__(256) void k_bn_act2(float* __restrict__ Y)
{
    size_t i4 = (size_t)blockIdx.x * blockDim.x + threadIdx.x;
    int c4 = (int)(i4 & (C2 / 4 - 1)) * 4;
    float4 v  = ((float4*)Y)[i4];
    float4 av = *(const float4*)&g_ab[2 * C1 + c4];
    float4 cv = *(const float4*)&g_ab[2 * C1 + C2 + c4];
    v.x = lrelu(fmaf(av.x, v.x, cv.x));
    v.y = lrelu(fmaf(av.y, v.y, cv.y));
    v.z = lrelu(fmaf(av.z, v.z, cv.z));
    v.w = lrelu(fmaf(av.w, v.w, cv.w));
    ((float4*)Y)[i4] = v;
}

// ============================================================
extern "C" void kernel_launch(void* const* d_in, const int* in_sizes, int n_in,
                              void* d_out, int out_size)
{
    (void)in_sizes; (void)n_in; (void)out_size;
    const float* E0 = (const float*)d_in[0];
    const float* E1 = (const float*)d_in[1];
    const float* P  = (const float*)d_in[2];
    const float* W1 = (const float*)d_in[3];
    const float* g1 = (const float*)d_in[4];
    const float* b1 = (const float*)d_in[5];
    const float* W2 = (const float*)d_in[6];
    const float* g2 = (const float*)d_in[7];
    const float* b2 = (const float*)d_in[8];
    float* out = (float*)d_out;

    cudaFuncSetAttribute(k1_mma,  cudaFuncAttributeMaxDynamicSharedMemorySize, 81920);
    cudaFuncSetAttribute(k_gemm1, cudaFuncAttributeMaxDynamicSharedMemorySize, 81920);
    cudaFuncSetAttribute(k_gemm2, cudaFuncAttributeMaxDynamicSharedMemorySize, 81920);

    // 0. one-time conversions (single combined weight split + P split)
    kW_split<<<192, 256>>>(W1, W2);
    kP_split<<<dim3(MB, 8), 256>>>(P);

    // 1. edge aggregation (batch-local CTA order, 3-stage B ring) -> g_Xs
    k1_mma<<<dim3(8, MB), 256, 81920>>>(E0, E1);

    // 2. GEMM1 (R13 grid ordering) + fused BN1 stats
    k_gemm1<<<dim3(MTOT / 128, 2), 256, 81920>>>();
    k_finalizeF<C1><<<C1, 256>>>(g1, b1, 0);

    // 3. GEMM2 (BN1+LReLU on load) + fused BN2 stats
    k_gemm2<<<dim3(MTOT / 128, 1), 256, 81920>>>(out);
    k_finalizeF<C2><<<C2, 256>>>(g2, b2, 2 * C1);

    // 4. in-place BN2 + LReLU
    k_bn_act2<<<16384, 256>>>(out);
}